// round 3
// baseline (speedup 1.0000x reference)
#include <cuda_runtime.h>

// ---------------------------------------------------------------------------
// CausalSelfAttentionWithBias: B=4, T=2048, C=1024, H=16, D=64, fp32
// Stage 1: qkv = x @ W_attn + b_attn  -> scatter to q/k/v [B,H,T,D] (+head bias,
//          q pre-scaled by 1/sqrt(D))
// Stage 2: causal flash attention -> y [B,T,C]
// Stage 3: out = y @ W_proj + b_proj
// ---------------------------------------------------------------------------

#define M1   8192
#define K1   1024
#define N1   3072
#define N2   1024
#define TT   2048
#define HH   16
#define DD   64

#define BM 128
#define BN 128
#define BK 8
#define TM 8
#define TN 8

// scratch (allocation-free: __device__ globals)
__device__ float g_q[4 * HH * TT * DD];
__device__ float g_k[4 * HH * TT * DD];
__device__ float g_v[4 * HH * TT * DD];
__device__ float g_y[4 * TT * 1024];

// ---------------------------------------------------------------------------
// Stage 1: QKV GEMM with fused bias + head-bias + q-scale, scatter epilogue
// ---------------------------------------------------------------------------
__global__ __launch_bounds__(256)
void gemm_qkv_kernel(const float* __restrict__ A,      // x [8192,1024]
                     const float* __restrict__ B,      // W_attn [1024,3072]
                     const float* __restrict__ b_attn, // [3072]
                     const float* __restrict__ bQ,     // [16*64]
                     const float* __restrict__ bK,
                     const float* __restrict__ bV)
{
    __shared__ float As[BK][BM];
    __shared__ float Bs[BK][BN];

    const int tid  = threadIdx.x;
    const int cRow = blockIdx.y;
    const int cCol = blockIdx.x;
    const int threadCol = tid % 16;
    const int threadRow = tid / 16;

    const float* Ab = A + cRow * BM * K1;
    const float* Bb = B + cCol * BN;

    const int innerRowA = tid / 2,  innerColA = tid % 2;   // A float4: [128][8]
    const int innerRowB = tid / 32, innerColB = tid % 32;  // B float4: [8][128]

    float acc[TM][TN] = {};
    float regM[TM], regN[TN];

    for (int kb = 0; kb < K1; kb += BK) {
        float4 a4 = *(const float4*)(Ab + innerRowA * K1 + kb + innerColA * 4);
        As[innerColA * 4 + 0][innerRowA] = a4.x;
        As[innerColA * 4 + 1][innerRowA] = a4.y;
        As[innerColA * 4 + 2][innerRowA] = a4.z;
        As[innerColA * 4 + 3][innerRowA] = a4.w;
        *(float4*)(&Bs[innerRowB][innerColB * 4]) =
            *(const float4*)(Bb + (kb + innerRowB) * N1 + innerColB * 4);
        __syncthreads();

        #pragma unroll
        for (int k = 0; k < BK; k++) {
            #pragma unroll
            for (int i = 0; i < TM; i++) regM[i] = As[k][threadRow * TM + i];
            #pragma unroll
            for (int j = 0; j < TN; j++) regN[j] = Bs[k][threadCol * TN + j];
            #pragma unroll
            for (int i = 0; i < TM; i++)
                #pragma unroll
                for (int j = 0; j < TN; j++)
                    acc[i][j] += regM[i] * regN[j];
        }
        __syncthreads();
    }

    // epilogue: scatter to q/k/v [B,H,T,D]
    const int col0  = cCol * BN + threadCol * TN;
    const int which = col0 >> 10;        // 0=q,1=k,2=v (128-col block never crosses)
    const int cc0   = col0 & 1023;
    const int h     = cc0 >> 6;
    const int d0    = cc0 & 63;          // 8 cols never cross a 64-boundary

    const float* hb = (which == 0 ? bQ : (which == 1 ? bK : bV)) + h * 64 + d0;
    float* dstBase  = (which == 0 ? g_q : (which == 1 ? g_k : g_v));
    const float scale = (which == 0) ? 0.125f : 1.0f;   // 1/sqrt(64)

    float bias[TN];
    #pragma unroll
    for (int j = 0; j < TN; j++) bias[j] = b_attn[col0 + j] + hb[j];

    #pragma unroll
    for (int i = 0; i < TM; i++) {
        const int m = cRow * BM + threadRow * TM + i;
        const int b = m >> 11, t = m & 2047;
        float* dst = dstBase + ((size_t)(b * HH + h) * TT + t) * DD + d0;
        #pragma unroll
        for (int j = 0; j < TN; j++)
            dst[j] = (acc[i][j] + bias[j]) * scale;
    }
}

// ---------------------------------------------------------------------------
// Stage 2: causal flash attention, 64x64 tiles, fp32
// block = 256 threads: 64 q-rows x 4 lanes; lane c owns k-cols/out-dims c*16..
// ---------------------------------------------------------------------------
__global__ __launch_bounds__(256)
void attn_kernel()
{
    __shared__ float Ks[64 * 64];
    __shared__ float Vs[64 * 64];

    const int tid = threadIdx.x;
    const int bh  = blockIdx.y;       // b*16 + h
    const int qt  = blockIdx.x;       // q tile index
    const int q0  = qt * 64;
    const int row = tid >> 2;
    const int c   = tid & 3;

    // Q row into registers (pre-scaled by 1/sqrt(D) in stage 1)
    float4 qr[16];
    const float4* qrow = (const float4*)(g_q + ((size_t)bh * TT + q0 + row) * DD);
    #pragma unroll
    for (int i = 0; i < 16; i++) qr[i] = qrow[i];

    float o[16];
    #pragma unroll
    for (int i = 0; i < 16; i++) o[i] = 0.f;
    float mval = -1e30f, l = 0.f;

    const float4* kbase = (const float4*)(g_k + (size_t)bh * TT * DD);
    const float4* vbase = (const float4*)(g_v + (size_t)bh * TT * DD);
    float4* Ks4 = (float4*)Ks;
    float4* Vs4 = (float4*)Vs;

    for (int tIdx = 0; tIdx <= qt; ++tIdx) {
        __syncthreads();
        const int kof = tIdx * 1024;  // float4 units: 64 rows * 16
        #pragma unroll
        for (int i = 0; i < 4; i++) {
            Ks4[tid + i * 256] = kbase[kof + tid + i * 256];
            Vs4[tid + i * 256] = vbase[kof + tid + i * 256];
        }
        __syncthreads();

        // scores: s[j] = q_row . k_{c*16+j}
        float s[16];
        #pragma unroll
        for (int j = 0; j < 16; j++) {
            const float4* krow = (const float4*)(Ks + (c * 16 + j) * 64);
            float a0 = 0.f, a1 = 0.f, a2 = 0.f, a3 = 0.f;
            #pragma unroll
            for (int d = 0; d < 16; d += 4) {
                float4 k0 = krow[d + 0], k1 = krow[d + 1], k2 = krow[d + 2], k3 = krow[d + 3];
                a0 += qr[d+0].x*k0.x + qr[d+0].y*k0.y + qr[d+0].z*k0.z + qr[d+0].w*k0.w;
                a1 += qr[d+1].x*k1.x + qr[d+1].y*k1.y + qr[d+1].z*k1.z + qr[d+1].w*k1.w;
                a2 += qr[d+2].x*k2.x + qr[d+2].y*k2.y + qr[d+2].z*k2.z + qr[d+2].w*k2.w;
                a3 += qr[d+3].x*k3.x + qr[d+3].y*k3.y + qr[d+3].z*k3.z + qr[d+3].w*k3.w;
            }
            s[j] = (a0 + a1) + (a2 + a3);
        }

        if (tIdx == qt) {   // diagonal tile: mask k > q
            #pragma unroll
            for (int j = 0; j < 16; j++)
                if (c * 16 + j > row) s[j] = -1e30f;
        }

        // online softmax (row = 4 lanes)
        float mt = s[0];
        #pragma unroll
        for (int j = 1; j < 16; j++) mt = fmaxf(mt, s[j]);
        mt = fmaxf(mt, __shfl_xor_sync(0xffffffffu, mt, 1));
        mt = fmaxf(mt, __shfl_xor_sync(0xffffffffu, mt, 2));
        const float mnew = fmaxf(mval, mt);
        const float corr = __expf(mval - mnew);
        float ls = 0.f;
        #pragma unroll
        for (int j = 0; j < 16; j++) { s[j] = __expf(s[j] - mnew); ls += s[j]; }
        ls += __shfl_xor_sync(0xffffffffu, ls, 1);
        ls += __shfl_xor_sync(0xffffffffu, ls, 2);
        l = l * corr + ls;
        mval = mnew;
        #pragma unroll
        for (int i = 0; i < 16; i++) o[i] *= corr;

        // PV: broadcast p within the 4-lane row group via shfl(width=4)
        #pragma unroll
        for (int jo = 0; jo < 4; jo++) {
            #pragma unroll
            for (int ji = 0; ji < 16; ji++) {
                const float p = __shfl_sync(0xffffffffu, s[ji], jo, 4);
                const float4* vr = (const float4*)(Vs + (jo * 16 + ji) * 64 + c * 16);
                float4 a0 = vr[0], a1 = vr[1], a2 = vr[2], a3 = vr[3];
                o[0]  += p * a0.x; o[1]  += p * a0.y; o[2]  += p * a0.z; o[3]  += p * a0.w;
                o[4]  += p * a1.x; o[5]  += p * a1.y; o[6]  += p * a1.z; o[7]  += p * a1.w;
                o[8]  += p * a2.x; o[9]  += p * a2.y; o[10] += p * a2.z; o[11] += p * a2.w;
                o[12] += p * a3.x; o[13] += p * a3.y; o[14] += p * a3.z; o[15] += p * a3.w;
            }
        }
    }

    const float inv = 1.f / l;
    const int b = bh >> 4, h = bh & 15;
    float4* yp = (float4*)(g_y + ((size_t)(b * TT) + q0 + row) * 1024 + h * 64 + c * 16);
    #pragma unroll
    for (int i = 0; i < 4; i++) {
        float4 w;
        w.x = o[i*4+0] * inv; w.y = o[i*4+1] * inv;
        w.z = o[i*4+2] * inv; w.w = o[i*4+3] * inv;
        yp[i] = w;
    }
}

// ---------------------------------------------------------------------------
// Stage 3: output projection GEMM + bias
// ---------------------------------------------------------------------------
__global__ __launch_bounds__(256)
void gemm_proj_kernel(const float* __restrict__ B,      // W_proj [1024,1024]
                      const float* __restrict__ b_proj, // [1024]
                      float* __restrict__ out)          // [8192,1024]
{
    __shared__ float As[BK][BM];
    __shared__ float Bs[BK][BN];

    const int tid  = threadIdx.x;
    const int cRow = blockIdx.y;
    const int cCol = blockIdx.x;
    const int threadCol = tid % 16;
    const int threadRow = tid / 16;

    const float* Ab = g_y + cRow * BM * N2;
    const float* Bb = B + cCol * BN;

    const int innerRowA = tid / 2,  innerColA = tid % 2;
    const int innerRowB = tid / 32, innerColB = tid % 32;

    float acc[TM][TN] = {};
    float regM[TM], regN[TN];

    for (int kb = 0; kb < N2; kb += BK) {
        float4 a4 = *(const float4*)(Ab + innerRowA * N2 + kb + innerColA * 4);
        As[innerColA * 4 + 0][innerRowA] = a4.x;
        As[innerColA * 4 + 1][innerRowA] = a4.y;
        As[innerColA * 4 + 2][innerRowA] = a4.z;
        As[innerColA * 4 + 3][innerRowA] = a4.w;
        *(float4*)(&Bs[innerRowB][innerColB * 4]) =
            *(const float4*)(Bb + (kb + innerRowB) * N2 + innerColB * 4);
        __syncthreads();

        #pragma unroll
        for (int k = 0; k < BK; k++) {
            #pragma unroll
            for (int i = 0; i < TM; i++) regM[i] = As[k][threadRow * TM + i];
            #pragma unroll
            for (int j = 0; j < TN; j++) regN[j] = Bs[k][threadCol * TN + j];
            #pragma unroll
            for (int i = 0; i < TM; i++)
                #pragma unroll
                for (int j = 0; j < TN; j++)
                    acc[i][j] += regM[i] * regN[j];
        }
        __syncthreads();
    }

    const int col0 = cCol * BN + threadCol * TN;
    float bias[TN];
    #pragma unroll
    for (int j = 0; j < TN; j++) bias[j] = b_proj[col0 + j];

    #pragma unroll
    for (int i = 0; i < TM; i++) {
        const int m = cRow * BM + threadRow * TM + i;
        float* dst = out + (size_t)m * N2 + col0;
        #pragma unroll
        for (int j = 0; j < TN; j++)
            dst[j] = acc[i][j] + bias[j];
    }
}

// ---------------------------------------------------------------------------
extern "C" void kernel_launch(void* const* d_in, const int* in_sizes, int n_in,
                              void* d_out, int out_size)
{
    (void)in_sizes; (void)n_in; (void)out_size;
    const float* x      = (const float*)d_in[0];
    const float* W_attn = (const float*)d_in[1];
    const float* b_attn = (const float*)d_in[2];
    const float* W_proj = (const float*)d_in[3];
    const float* b_proj = (const float*)d_in[4];
    const float* bQ     = (const float*)d_in[5];
    const float* bK     = (const float*)d_in[6];
    const float* bV     = (const float*)d_in[7];
    float* out = (float*)d_out;

    dim3 g1(N1 / BN, M1 / BM);   // (24, 64)
    gemm_qkv_kernel<<<g1, 256>>>(x, W_attn, b_attn, bQ, bK, bV);

    dim3 ga(TT / 64, 4 * HH);    // (32, 64)
    attn_kernel<<<ga, 256>>>();

    dim3 g2(N2 / BN, M1 / BM);   // (8, 64)
    gemm_proj_kernel<<<g2, 256>>>(W_proj, b_proj, out);
}

// round 4
// speedup vs baseline: 1.0005x; 1.0005x over previous
#include <cuda_runtime.h>

// ---------------------------------------------------------------------------
// CausalSelfAttentionWithBias: B=4, T=2048, C=1024, H=16, D=64, fp32
// Stage 1: qkv = x @ W_attn + b_attn  -> scatter to q/k/v [B,H,T,D] (+head bias,
//          q pre-scaled by 1/sqrt(D))
// Stage 2: causal flash attention -> y [B,T,C]
// Stage 3: out = y @ W_proj + b_proj
// ---------------------------------------------------------------------------

#define M1   8192
#define K1   1024
#define N1   3072
#define N2   1024
#define TT   2048
#define HH   16
#define DD   64

#define BM 128
#define BN 128
#define BK 8
#define TM 8
#define TN 8

// scratch (allocation-free: __device__ globals)
__device__ float g_q[4 * HH * TT * DD];
__device__ float g_k[4 * HH * TT * DD];
__device__ float g_v[4 * HH * TT * DD];
__device__ float g_y[4 * TT * 1024];

// ---------------------------------------------------------------------------
// Stage 1: QKV GEMM with fused bias + head-bias + q-scale, scatter epilogue
// ---------------------------------------------------------------------------
__global__ __launch_bounds__(256)
void gemm_qkv_kernel(const float* __restrict__ A,      // x [8192,1024]
                     const float* __restrict__ B,      // W_attn [1024,3072]
                     const float* __restrict__ b_attn, // [3072]
                     const float* __restrict__ bQ,     // [16*64]
                     const float* __restrict__ bK,
                     const float* __restrict__ bV)
{
    __shared__ float As[BK][BM];
    __shared__ float Bs[BK][BN];

    const int tid  = threadIdx.x;
    const int cRow = blockIdx.y;
    const int cCol = blockIdx.x;
    const int threadCol = tid % 16;
    const int threadRow = tid / 16;

    const float* Ab = A + cRow * BM * K1;
    const float* Bb = B + cCol * BN;

    const int innerRowA = tid / 2,  innerColA = tid % 2;   // A float4: [128][8]
    const int innerRowB = tid / 32, innerColB = tid % 32;  // B float4: [8][128]

    float acc[TM][TN] = {};
    float regM[TM], regN[TN];

    for (int kb = 0; kb < K1; kb += BK) {
        float4 a4 = *(const float4*)(Ab + innerRowA * K1 + kb + innerColA * 4);
        As[innerColA * 4 + 0][innerRowA] = a4.x;
        As[innerColA * 4 + 1][innerRowA] = a4.y;
        As[innerColA * 4 + 2][innerRowA] = a4.z;
        As[innerColA * 4 + 3][innerRowA] = a4.w;
        *(float4*)(&Bs[innerRowB][innerColB * 4]) =
            *(const float4*)(Bb + (kb + innerRowB) * N1 + innerColB * 4);
        __syncthreads();

        #pragma unroll
        for (int k = 0; k < BK; k++) {
            #pragma unroll
            for (int i = 0; i < TM; i++) regM[i] = As[k][threadRow * TM + i];
            #pragma unroll
            for (int j = 0; j < TN; j++) regN[j] = Bs[k][threadCol * TN + j];
            #pragma unroll
            for (int i = 0; i < TM; i++)
                #pragma unroll
                for (int j = 0; j < TN; j++)
                    acc[i][j] += regM[i] * regN[j];
        }
        __syncthreads();
    }

    // epilogue: scatter to q/k/v [B,H,T,D]
    const int col0  = cCol * BN + threadCol * TN;
    const int which = col0 >> 10;        // 0=q,1=k,2=v (128-col block never crosses)
    const int cc0   = col0 & 1023;
    const int h     = cc0 >> 6;
    const int d0    = cc0 & 63;          // 8 cols never cross a 64-boundary

    const float* hb = (which == 0 ? bQ : (which == 1 ? bK : bV)) + h * 64 + d0;
    float* dstBase  = (which == 0 ? g_q : (which == 1 ? g_k : g_v));
    const float scale = (which == 0) ? 0.125f : 1.0f;   // 1/sqrt(64)

    float bias[TN];
    #pragma unroll
    for (int j = 0; j < TN; j++) bias[j] = b_attn[col0 + j] + hb[j];

    #pragma unroll
    for (int i = 0; i < TM; i++) {
        const int m = cRow * BM + threadRow * TM + i;
        const int b = m >> 11, t = m & 2047;
        float* dst = dstBase + ((size_t)(b * HH + h) * TT + t) * DD + d0;
        #pragma unroll
        for (int j = 0; j < TN; j++)
            dst[j] = (acc[i][j] + bias[j]) * scale;
    }
}

// ---------------------------------------------------------------------------
// Stage 2: causal flash attention, 64x64 tiles, fp32
// block = 256 threads: 64 q-rows x 4 lanes; lane c owns k-cols/out-dims c*16..
// ---------------------------------------------------------------------------
__global__ __launch_bounds__(256)
void attn_kernel()
{
    __shared__ float Ks[64 * 64];
    __shared__ float Vs[64 * 64];

    const int tid = threadIdx.x;
    const int bh  = blockIdx.y;       // b*16 + h
    const int qt  = blockIdx.x;       // q tile index
    const int q0  = qt * 64;
    const int row = tid >> 2;
    const int c   = tid & 3;

    // Q row into registers (pre-scaled by 1/sqrt(D) in stage 1)
    float4 qr[16];
    const float4* qrow = (const float4*)(g_q + ((size_t)bh * TT + q0 + row) * DD);
    #pragma unroll
    for (int i = 0; i < 16; i++) qr[i] = qrow[i];

    float o[16];
    #pragma unroll
    for (int i = 0; i < 16; i++) o[i] = 0.f;
    float mval = -1e30f, l = 0.f;

    const float4* kbase = (const float4*)(g_k + (size_t)bh * TT * DD);
    const float4* vbase = (const float4*)(g_v + (size_t)bh * TT * DD);
    float4* Ks4 = (float4*)Ks;
    float4* Vs4 = (float4*)Vs;

    for (int tIdx = 0; tIdx <= qt; ++tIdx) {
        __syncthreads();
        const int kof = tIdx * 1024;  // float4 units: 64 rows * 16
        #pragma unroll
        for (int i = 0; i < 4; i++) {
            Ks4[tid + i * 256] = kbase[kof + tid + i * 256];
            Vs4[tid + i * 256] = vbase[kof + tid + i * 256];
        }
        __syncthreads();

        // scores: s[j] = q_row . k_{c*16+j}
        float s[16];
        #pragma unroll
        for (int j = 0; j < 16; j++) {
            const float4* krow = (const float4*)(Ks + (c * 16 + j) * 64);
            float a0 = 0.f, a1 = 0.f, a2 = 0.f, a3 = 0.f;
            #pragma unroll
            for (int d = 0; d < 16; d += 4) {
                float4 k0 = krow[d + 0], k1 = krow[d + 1], k2 = krow[d + 2], k3 = krow[d + 3];
                a0 += qr[d+0].x*k0.x + qr[d+0].y*k0.y + qr[d+0].z*k0.z + qr[d+0].w*k0.w;
                a1 += qr[d+1].x*k1.x + qr[d+1].y*k1.y + qr[d+1].z*k1.z + qr[d+1].w*k1.w;
                a2 += qr[d+2].x*k2.x + qr[d+2].y*k2.y + qr[d+2].z*k2.z + qr[d+2].w*k2.w;
                a3 += qr[d+3].x*k3.x + qr[d+3].y*k3.y + qr[d+3].z*k3.z + qr[d+3].w*k3.w;
            }
            s[j] = (a0 + a1) + (a2 + a3);
        }

        if (tIdx == qt) {   // diagonal tile: mask k > q
            #pragma unroll
            for (int j = 0; j < 16; j++)
                if (c * 16 + j > row) s[j] = -1e30f;
        }

        // online softmax (row = 4 lanes)
        float mt = s[0];
        #pragma unroll
        for (int j = 1; j < 16; j++) mt = fmaxf(mt, s[j]);
        mt = fmaxf(mt, __shfl_xor_sync(0xffffffffu, mt, 1));
        mt = fmaxf(mt, __shfl_xor_sync(0xffffffffu, mt, 2));
        const float mnew = fmaxf(mval, mt);
        const float corr = __expf(mval - mnew);
        float ls = 0.f;
        #pragma unroll
        for (int j = 0; j < 16; j++) { s[j] = __expf(s[j] - mnew); ls += s[j]; }
        ls += __shfl_xor_sync(0xffffffffu, ls, 1);
        ls += __shfl_xor_sync(0xffffffffu, ls, 2);
        l = l * corr + ls;
        mval = mnew;
        #pragma unroll
        for (int i = 0; i < 16; i++) o[i] *= corr;

        // PV: broadcast p within the 4-lane row group via shfl(width=4)
        #pragma unroll
        for (int jo = 0; jo < 4; jo++) {
            #pragma unroll
            for (int ji = 0; ji < 16; ji++) {
                const float p = __shfl_sync(0xffffffffu, s[ji], jo, 4);
                const float4* vr = (const float4*)(Vs + (jo * 16 + ji) * 64 + c * 16);
                float4 a0 = vr[0], a1 = vr[1], a2 = vr[2], a3 = vr[3];
                o[0]  += p * a0.x; o[1]  += p * a0.y; o[2]  += p * a0.z; o[3]  += p * a0.w;
                o[4]  += p * a1.x; o[5]  += p * a1.y; o[6]  += p * a1.z; o[7]  += p * a1.w;
                o[8]  += p * a2.x; o[9]  += p * a2.y; o[10] += p * a2.z; o[11] += p * a2.w;
                o[12] += p * a3.x; o[13] += p * a3.y; o[14] += p * a3.z; o[15] += p * a3.w;
            }
        }
    }

    const float inv = 1.f / l;
    const int b = bh >> 4, h = bh & 15;
    float4* yp = (float4*)(g_y + ((size_t)(b * TT) + q0 + row) * 1024 + h * 64 + c * 16);
    #pragma unroll
    for (int i = 0; i < 4; i++) {
        float4 w;
        w.x = o[i*4+0] * inv; w.y = o[i*4+1] * inv;
        w.z = o[i*4+2] * inv; w.w = o[i*4+3] * inv;
        yp[i] = w;
    }
}

// ---------------------------------------------------------------------------
// Stage 3: output projection GEMM + bias
// ---------------------------------------------------------------------------
__global__ __launch_bounds__(256)
void gemm_proj_kernel(const float* __restrict__ B,      // W_proj [1024,1024]
                      const float* __restrict__ b_proj, // [1024]
                      float* __restrict__ out)          // [8192,1024]
{
    __shared__ float As[BK][BM];
    __shared__ float Bs[BK][BN];

    const int tid  = threadIdx.x;
    const int cRow = blockIdx.y;
    const int cCol = blockIdx.x;
    const int threadCol = tid % 16;
    const int threadRow = tid / 16;

    const float* Ab = g_y + cRow * BM * N2;
    const float* Bb = B + cCol * BN;

    const int innerRowA = tid / 2,  innerColA = tid % 2;
    const int innerRowB = tid / 32, innerColB = tid % 32;

    float acc[TM][TN] = {};
    float regM[TM], regN[TN];

    for (int kb = 0; kb < N2; kb += BK) {
        float4 a4 = *(const float4*)(Ab + innerRowA * N2 + kb + innerColA * 4);
        As[innerColA * 4 + 0][innerRowA] = a4.x;
        As[innerColA * 4 + 1][innerRowA] = a4.y;
        As[innerColA * 4 + 2][innerRowA] = a4.z;
        As[innerColA * 4 + 3][innerRowA] = a4.w;
        *(float4*)(&Bs[innerRowB][innerColB * 4]) =
            *(const float4*)(Bb + (kb + innerRowB) * N2 + innerColB * 4);
        __syncthreads();

        #pragma unroll
        for (int k = 0; k < BK; k++) {
            #pragma unroll
            for (int i = 0; i < TM; i++) regM[i] = As[k][threadRow * TM + i];
            #pragma unroll
            for (int j = 0; j < TN; j++) regN[j] = Bs[k][threadCol * TN + j];
            #pragma unroll
            for (int i = 0; i < TM; i++)
                #pragma unroll
                for (int j = 0; j < TN; j++)
                    acc[i][j] += regM[i] * regN[j];
        }
        __syncthreads();
    }

    const int col0 = cCol * BN + threadCol * TN;
    float bias[TN];
    #pragma unroll
    for (int j = 0; j < TN; j++) bias[j] = b_proj[col0 + j];

    #pragma unroll
    for (int i = 0; i < TM; i++) {
        const int m = cRow * BM + threadRow * TM + i;
        float* dst = out + (size_t)m * N2 + col0;
        #pragma unroll
        for (int j = 0; j < TN; j++)
            dst[j] = acc[i][j] + bias[j];
    }
}

// ---------------------------------------------------------------------------
extern "C" void kernel_launch(void* const* d_in, const int* in_sizes, int n_in,
                              void* d_out, int out_size)
{
    (void)in_sizes; (void)n_in; (void)out_size;
    const float* x      = (const float*)d_in[0];
    const float* W_attn = (const float*)d_in[1];
    const float* b_attn = (const float*)d_in[2];
    const float* W_proj = (const float*)d_in[3];
    const float* b_proj = (const float*)d_in[4];
    const float* bQ     = (const float*)d_in[5];
    const float* bK     = (const float*)d_in[6];
    const float* bV     = (const float*)d_in[7];
    float* out = (float*)d_out;

    dim3 g1(N1 / BN, M1 / BM);   // (24, 64)
    gemm_qkv_kernel<<<g1, 256>>>(x, W_attn, b_attn, bQ, bK, bV);

    dim3 ga(TT / 64, 4 * HH);    // (32, 64)
    attn_kernel<<<ga, 256>>>();

    dim3 g2(N2 / BN, M1 / BM);   // (8, 64)
    gemm_proj_kernel<<<g2, 256>>>(W_proj, b_proj, out);
}

// round 5
// speedup vs baseline: 8.6743x; 8.6696x over previous
#include <cuda_runtime.h>

// ---------------------------------------------------------------------------
// CausalSelfAttentionWithBias: B=4, T=2048, C=1024, H=16, D=64
// All matmuls on tensor cores via tf32 mma.sync.m16n8k8 (fp32 accumulate).
// Stage 1: qkv = x @ W_attn + b_attn -> scatter q/k/v [B,H,T,D] (+head bias,
//          q pre-scaled by 1/sqrt(D))
// Stage 2: causal flash attention (tf32 mma QK^T and PV) -> y [B,T,C]
// Stage 3: out = y @ W_proj + b_proj
// ---------------------------------------------------------------------------

#define TT 2048
#define HH 16

__device__ float g_q[4 * HH * TT * 64];
__device__ float g_k[4 * HH * TT * 64];
__device__ float g_v[4 * HH * TT * 64];
__device__ float g_y[4 * TT * 1024];

__device__ __forceinline__ unsigned f2t(float x) {
    unsigned u; asm("cvt.rna.tf32.f32 %0, %1;" : "=r"(u) : "f"(x)); return u;
}

__device__ __forceinline__ void mma8(float* d, const unsigned* a, const unsigned* b) {
    asm volatile(
        "mma.sync.aligned.m16n8k8.row.col.f32.tf32.tf32.f32 "
        "{%0,%1,%2,%3}, {%4,%5,%6,%7}, {%8,%9}, {%0,%1,%2,%3};"
        : "+f"(d[0]), "+f"(d[1]), "+f"(d[2]), "+f"(d[3])
        : "r"(a[0]), "r"(a[1]), "r"(a[2]), "r"(a[3]), "r"(b[0]), "r"(b[1]));
}

// ---------------------------------------------------------------------------
// Stage 1: QKV GEMM  (M=8192, K=1024, N=3072), tf32 mma
// block 128x128, BK=16, 8 warps (2x4), warp tile 64x32
// ---------------------------------------------------------------------------
#define SA 20    // As row stride (words): banks (20r+t)%32 distinct for r0..7,t0..3
#define SB 136   // Bs row stride (words): banks (8k+g)%32 distinct

__global__ __launch_bounds__(256)
void gemm_qkv_kernel(const float* __restrict__ A,      // x [8192,1024]
                     const float* __restrict__ B,      // W_attn [1024,3072]
                     const float* __restrict__ b_attn,
                     const float* __restrict__ bQ,
                     const float* __restrict__ bK,
                     const float* __restrict__ bV)
{
    __shared__ unsigned As[128 * SA];
    __shared__ unsigned Bs[16 * SB];

    const int tid = threadIdx.x;
    const int wid = tid >> 5, lane = tid & 31;
    const int g = lane >> 2, t = lane & 3;
    const int mBase = (wid >> 2) * 64, nBase = (wid & 3) * 32;
    const int cRow = blockIdx.y, cCol = blockIdx.x;

    float acc[4][4][4] = {};

    const float* Ag = A + (size_t)cRow * 128 * 1024;
    const float* Bg = B + cCol * 128;

    for (int kb = 0; kb < 1024; kb += 16) {
        #pragma unroll
        for (int it = 0; it < 2; it++) {
            int id = tid + it * 256;            // 0..511 : A 128x16
            int r = id >> 2, c4 = id & 3;
            float4 v = *(const float4*)(Ag + (size_t)r * 1024 + kb + c4 * 4);
            unsigned* p = &As[r * SA + c4 * 4];
            p[0] = f2t(v.x); p[1] = f2t(v.y); p[2] = f2t(v.z); p[3] = f2t(v.w);
        }
        #pragma unroll
        for (int it = 0; it < 2; it++) {
            int id = tid + it * 256;            // 0..511 : B 16x128
            int r = id >> 5, c4 = id & 31;
            float4 v = *(const float4*)(Bg + (size_t)(kb + r) * 3072 + c4 * 4);
            unsigned* p = &Bs[r * SB + c4 * 4];
            p[0] = f2t(v.x); p[1] = f2t(v.y); p[2] = f2t(v.z); p[3] = f2t(v.w);
        }
        __syncthreads();

        #pragma unroll
        for (int kk = 0; kk < 2; kk++) {
            const int k0 = kk * 8;
            unsigned af[4][4], bf[4][2];
            #pragma unroll
            for (int i = 0; i < 4; i++) {
                int r0 = mBase + i * 16 + g;
                af[i][0] = As[r0 * SA + k0 + t];
                af[i][1] = As[(r0 + 8) * SA + k0 + t];
                af[i][2] = As[r0 * SA + k0 + t + 4];
                af[i][3] = As[(r0 + 8) * SA + k0 + t + 4];
            }
            #pragma unroll
            for (int j = 0; j < 4; j++) {
                int c0 = nBase + j * 8 + g;
                bf[j][0] = Bs[(k0 + t) * SB + c0];
                bf[j][1] = Bs[(k0 + t + 4) * SB + c0];
            }
            #pragma unroll
            for (int i = 0; i < 4; i++)
                #pragma unroll
                for (int j = 0; j < 4; j++)
                    mma8(acc[i][j], af[i], bf[j]);
        }
        __syncthreads();
    }

    // epilogue: scatter to q/k/v with fused biases + q scale
    const int colW  = cCol * 128 + nBase;   // warp col base (which/h warp-uniform)
    const int which = colW >> 10;
    const int h     = (colW & 1023) >> 6;
    float* dstBase  = which == 0 ? g_q : (which == 1 ? g_k : g_v);
    const float* hb = (which == 0 ? bQ : (which == 1 ? bK : bV)) + h * 64;
    const float scale = (which == 0) ? 0.125f : 1.0f;

    #pragma unroll
    for (int j = 0; j < 4; j++) {
        int col = colW + j * 8 + t * 2;
        int d0 = col & 63;
        float bb0 = (b_attn[col]     + hb[d0])     * scale;
        float bb1 = (b_attn[col + 1] + hb[d0 + 1]) * scale;
        #pragma unroll
        for (int i = 0; i < 4; i++) {
            int row0 = cRow * 128 + mBase + i * 16 + g;
            #pragma unroll
            for (int rh = 0; rh < 2; rh++) {
                int row = row0 + rh * 8;
                int b = row >> 11, tt_ = row & 2047;
                float2 o;
                o.x = acc[i][j][rh * 2 + 0] * scale + bb0;
                o.y = acc[i][j][rh * 2 + 1] * scale + bb1;
                *(float2*)(dstBase + (((size_t)(b * HH + h) * TT + tt_) << 6) + d0) = o;
            }
        }
    }
}

// ---------------------------------------------------------------------------
// Stage 2: causal flash attention, tf32 mma.
// block = 128 thr (4 warps); q-tile 64 rows, warp owns 16 q-rows.
// Ks aliased by per-warp P buffers after S is computed.
// ---------------------------------------------------------------------------
#define SQ 68    // Ks/Ps row stride: banks (4r+t)%32 distinct
#define SV 72    // Vs row stride: banks (8t+g)%32 distinct

__global__ __launch_bounds__(128)
void attn_kernel()
{
    __shared__ unsigned Ks[64 * SQ];   // 4352 words; reused as P (4 warps x 16 x SQ)
    __shared__ unsigned Vs[64 * SV];

    const int tid = threadIdx.x;
    const int w = tid >> 5, lane = tid & 31;
    const int g = lane >> 2, t = lane & 3;
    const int bh = blockIdx.y, qt = blockIdx.x;
    const int q0 = qt * 64;

    const float* qbase = g_q + (size_t)bh * TT * 64;
    const float* kbase = g_k + (size_t)bh * TT * 64;
    const float* vbase = g_v + (size_t)bh * TT * 64;

    // Q fragments (pre-scaled by 1/sqrt(D) in stage 1), held in regs
    unsigned qa[8][4];
    {
        const float* q0p = qbase + (size_t)(q0 + w * 16 + g) * 64;
        const float* q1p = q0p + 8 * 64;
        #pragma unroll
        for (int kk = 0; kk < 8; kk++) {
            qa[kk][0] = f2t(q0p[kk * 8 + t]);
            qa[kk][1] = f2t(q1p[kk * 8 + t]);
            qa[kk][2] = f2t(q0p[kk * 8 + t + 4]);
            qa[kk][3] = f2t(q1p[kk * 8 + t + 4]);
        }
    }

    float oacc[8][4] = {};
    float mrow[2] = {-1e30f, -1e30f};
    float lrow[2] = {0.f, 0.f};

    unsigned* Psw = Ks + w * 16 * SQ;   // this warp's P region (aliases Ks)

    for (int tI = 0; tI <= qt; tI++) {
        __syncthreads();   // prior PV (Ps/Vs reads) done before overwrite
        const float* kt = kbase + (size_t)tI * 64 * 64;
        const float* vt = vbase + (size_t)tI * 64 * 64;
        #pragma unroll
        for (int i = 0; i < 8; i++) {
            int id = tid + i * 128;            // 0..1023: 64x16 float4
            int r = id >> 4, c4 = id & 15;
            float4 kv = *(const float4*)(kt + r * 64 + c4 * 4);
            float4 vv = *(const float4*)(vt + r * 64 + c4 * 4);
            unsigned* kp = &Ks[r * SQ + c4 * 4];
            kp[0] = f2t(kv.x); kp[1] = f2t(kv.y); kp[2] = f2t(kv.z); kp[3] = f2t(kv.w);
            unsigned* vp = &Vs[r * SV + c4 * 4];
            vp[0] = f2t(vv.x); vp[1] = f2t(vv.y); vp[2] = f2t(vv.z); vp[3] = f2t(vv.w);
        }
        __syncthreads();

        // S = Q . K^T   (16 x 64 per warp)
        float sacc[8][4] = {};
        #pragma unroll
        for (int kk = 0; kk < 8; kk++) {
            const int k0 = kk * 8;
            #pragma unroll
            for (int j = 0; j < 8; j++) {
                unsigned bf[2];
                bf[0] = Ks[(j * 8 + g) * SQ + k0 + t];
                bf[1] = Ks[(j * 8 + g) * SQ + k0 + t + 4];
                mma8(sacc[j], qa[kk], bf);
            }
        }
        __syncthreads();   // all warps done reading Ks -> safe to write P

        // causal mask on diagonal tile (local coords within the 64-block)
        if (tI == qt) {
            #pragma unroll
            for (int j = 0; j < 8; j++)
                #pragma unroll
                for (int r = 0; r < 4; r++) {
                    int rq = w * 16 + g + (r >> 1) * 8;
                    int cq = j * 8 + t * 2 + (r & 1);
                    if (cq > rq) sacc[j][r] = -1e30f;
                }
        }

        // online softmax (row = 4 lanes sharing groupID)
        float corr[2];
        #pragma unroll
        for (int rh = 0; rh < 2; rh++) {
            float mt = -1e30f;
            #pragma unroll
            for (int j = 0; j < 8; j++)
                mt = fmaxf(mt, fmaxf(sacc[j][rh * 2], sacc[j][rh * 2 + 1]));
            mt = fmaxf(mt, __shfl_xor_sync(0xffffffffu, mt, 1));
            mt = fmaxf(mt, __shfl_xor_sync(0xffffffffu, mt, 2));
            float mn = fmaxf(mrow[rh], mt);
            corr[rh] = __expf(mrow[rh] - mn);
            mrow[rh] = mn;
        }
        float ls0 = 0.f, ls1 = 0.f;
        #pragma unroll
        for (int j = 0; j < 8; j++) {
            float p0 = __expf(sacc[j][0] - mrow[0]);
            float p1 = __expf(sacc[j][1] - mrow[0]);
            float p2 = __expf(sacc[j][2] - mrow[1]);
            float p3 = __expf(sacc[j][3] - mrow[1]);
            sacc[j][0] = p0; sacc[j][1] = p1; sacc[j][2] = p2; sacc[j][3] = p3;
            ls0 += p0 + p1; ls1 += p2 + p3;
        }
        ls0 += __shfl_xor_sync(0xffffffffu, ls0, 1);
        ls0 += __shfl_xor_sync(0xffffffffu, ls0, 2);
        ls1 += __shfl_xor_sync(0xffffffffu, ls1, 1);
        ls1 += __shfl_xor_sync(0xffffffffu, ls1, 2);
        lrow[0] = lrow[0] * corr[0] + ls0;
        lrow[1] = lrow[1] * corr[1] + ls1;

        #pragma unroll
        for (int j = 0; j < 8; j++) {
            oacc[j][0] *= corr[0]; oacc[j][1] *= corr[0];
            oacc[j][2] *= corr[1]; oacc[j][3] *= corr[1];
        }

        // P -> per-warp smem (tf32), C-frag layout -> row-major
        #pragma unroll
        for (int j = 0; j < 8; j++) {
            unsigned* p0 = &Psw[g * SQ + j * 8 + t * 2];
            p0[0] = f2t(sacc[j][0]); p0[1] = f2t(sacc[j][1]);
            unsigned* p1 = &Psw[(g + 8) * SQ + j * 8 + t * 2];
            p1[0] = f2t(sacc[j][2]); p1[1] = f2t(sacc[j][3]);
        }
        __syncwarp();

        // O += P . V
        #pragma unroll
        for (int kk = 0; kk < 8; kk++) {
            const int k0 = kk * 8;
            unsigned pa[4];
            pa[0] = Psw[g * SQ + k0 + t];
            pa[1] = Psw[(g + 8) * SQ + k0 + t];
            pa[2] = Psw[g * SQ + k0 + t + 4];
            pa[3] = Psw[(g + 8) * SQ + k0 + t + 4];
            #pragma unroll
            for (int j = 0; j < 8; j++) {
                unsigned vb[2];
                vb[0] = Vs[(k0 + t) * SV + j * 8 + g];
                vb[1] = Vs[(k0 + t + 4) * SV + j * 8 + g];
                mma8(oacc[j], pa, vb);
            }
        }
    }

    // write y [B,T,C]
    const int b = bh >> 4, h = bh & 15;
    const float inv0 = 1.f / lrow[0], inv1 = 1.f / lrow[1];
    float* yb = g_y + ((size_t)b * TT + q0 + w * 16) * 1024 + h * 64;
    #pragma unroll
    for (int j = 0; j < 8; j++) {
        float2 o0 = { oacc[j][0] * inv0, oacc[j][1] * inv0 };
        float2 o1 = { oacc[j][2] * inv1, oacc[j][3] * inv1 };
        *(float2*)(yb + (size_t)g * 1024 + j * 8 + t * 2) = o0;
        *(float2*)(yb + (size_t)(g + 8) * 1024 + j * 8 + t * 2) = o1;
    }
}

// ---------------------------------------------------------------------------
// Stage 3: out = y @ W_proj + b_proj  (M=8192, K=1024, N=1024), tf32 mma
// ---------------------------------------------------------------------------
__global__ __launch_bounds__(256)
void gemm_proj_kernel(const float* __restrict__ B,      // W_proj [1024,1024]
                      const float* __restrict__ b_proj,
                      float* __restrict__ out)
{
    __shared__ unsigned As[128 * SA];
    __shared__ unsigned Bs[16 * SB];

    const int tid = threadIdx.x;
    const int wid = tid >> 5, lane = tid & 31;
    const int g = lane >> 2, t = lane & 3;
    const int mBase = (wid >> 2) * 64, nBase = (wid & 3) * 32;
    const int cRow = blockIdx.y, cCol = blockIdx.x;

    float acc[4][4][4] = {};

    const float* Ag = g_y + (size_t)cRow * 128 * 1024;
    const float* Bg = B + cCol * 128;

    for (int kb = 0; kb < 1024; kb += 16) {
        #pragma unroll
        for (int it = 0; it < 2; it++) {
            int id = tid + it * 256;
            int r = id >> 2, c4 = id & 3;
            float4 v = *(const float4*)(Ag + (size_t)r * 1024 + kb + c4 * 4);
            unsigned* p = &As[r * SA + c4 * 4];
            p[0] = f2t(v.x); p[1] = f2t(v.y); p[2] = f2t(v.z); p[3] = f2t(v.w);
        }
        #pragma unroll
        for (int it = 0; it < 2; it++) {
            int id = tid + it * 256;
            int r = id >> 5, c4 = id & 31;
            float4 v = *(const float4*)(Bg + (size_t)(kb + r) * 1024 + c4 * 4);
            unsigned* p = &Bs[r * SB + c4 * 4];
            p[0] = f2t(v.x); p[1] = f2t(v.y); p[2] = f2t(v.z); p[3] = f2t(v.w);
        }
        __syncthreads();

        #pragma unroll
        for (int kk = 0; kk < 2; kk++) {
            const int k0 = kk * 8;
            unsigned af[4][4], bf[4][2];
            #pragma unroll
            for (int i = 0; i < 4; i++) {
                int r0 = mBase + i * 16 + g;
                af[i][0] = As[r0 * SA + k0 + t];
                af[i][1] = As[(r0 + 8) * SA + k0 + t];
                af[i][2] = As[r0 * SA + k0 + t + 4];
                af[i][3] = As[(r0 + 8) * SA + k0 + t + 4];
            }
            #pragma unroll
            for (int j = 0; j < 4; j++) {
                int c0 = nBase + j * 8 + g;
                bf[j][0] = Bs[(k0 + t) * SB + c0];
                bf[j][1] = Bs[(k0 + t + 4) * SB + c0];
            }
            #pragma unroll
            for (int i = 0; i < 4; i++)
                #pragma unroll
                for (int j = 0; j < 4; j++)
                    mma8(acc[i][j], af[i], bf[j]);
        }
        __syncthreads();
    }

    #pragma unroll
    for (int j = 0; j < 4; j++) {
        int col = cCol * 128 + nBase + j * 8 + t * 2;
        float bb0 = b_proj[col], bb1 = b_proj[col + 1];
        #pragma unroll
        for (int i = 0; i < 4; i++) {
            int row0 = cRow * 128 + mBase + i * 16 + g;
            #pragma unroll
            for (int rh = 0; rh < 2; rh++) {
                int row = row0 + rh * 8;
                float2 o;
                o.x = acc[i][j][rh * 2 + 0] + bb0;
                o.y = acc[i][j][rh * 2 + 1] + bb1;
                *(float2*)(out + (size_t)row * 1024 + col) = o;
            }
        }
    }
}

// ---------------------------------------------------------------------------
extern "C" void kernel_launch(void* const* d_in, const int* in_sizes, int n_in,
                              void* d_out, int out_size)
{
    (void)in_sizes; (void)n_in; (void)out_size;
    const float* x      = (const float*)d_in[0];
    const float* W_attn = (const float*)d_in[1];
    const float* b_attn = (const float*)d_in[2];
    const float* W_proj = (const float*)d_in[3];
    const float* b_proj = (const float*)d_in[4];
    const float* bQ     = (const float*)d_in[5];
    const float* bK     = (const float*)d_in[6];
    const float* bV     = (const float*)d_in[7];
    float* out = (float*)d_out;

    dim3 g1(24, 64);                 // 3072/128, 8192/128
    gemm_qkv_kernel<<<g1, 256>>>(x, W_attn, b_attn, bQ, bK, bV);

    dim3 ga(TT / 64, 4 * HH);        // (32, 64)
    attn_kernel<<<ga, 128>>>();

    dim3 g2(8, 64);                  // 1024/128, 8192/128
    gemm_proj_kernel<<<g2, 256>>>(W_proj, b_proj, out);
}

// round 6
// speedup vs baseline: 9.6533x; 1.1129x over previous
#include <cuda_runtime.h>

// ---------------------------------------------------------------------------
// CausalSelfAttentionWithBias: B=4, T=2048, C=1024, H=16, D=64
// tf32 mma.m16n8k8 everywhere; ldmatrix fragment feeds; prefetched GEMM fills.
// ---------------------------------------------------------------------------

#define TT 2048
#define HH 16

__device__ float g_q[4 * HH * TT * 64];
__device__ float g_k[4 * HH * TT * 64];
__device__ float g_v[4 * HH * TT * 64];
__device__ float g_y[4 * TT * 1024];

__device__ __forceinline__ unsigned f2t(float x) {
    unsigned u; asm("cvt.rna.tf32.f32 %0, %1;" : "=r"(u) : "f"(x)); return u;
}

__device__ __forceinline__ void mma8(float* d, const unsigned* a, const unsigned* b) {
    asm volatile(
        "mma.sync.aligned.m16n8k8.row.col.f32.tf32.tf32.f32 "
        "{%0,%1,%2,%3}, {%4,%5,%6,%7}, {%8,%9}, {%0,%1,%2,%3};"
        : "+f"(d[0]), "+f"(d[1]), "+f"(d[2]), "+f"(d[3])
        : "r"(a[0]), "r"(a[1]), "r"(a[2]), "r"(a[3]), "r"(b[0]), "r"(b[1]));
}

__device__ __forceinline__ unsigned sptr(const void* p) {
    return (unsigned)__cvta_generic_to_shared(p);
}

__device__ __forceinline__ void ldsm4(unsigned* r, unsigned addr) {
    asm volatile("ldmatrix.sync.aligned.m8n8.x4.shared.b16 {%0,%1,%2,%3}, [%4];"
        : "=r"(r[0]), "=r"(r[1]), "=r"(r[2]), "=r"(r[3]) : "r"(addr));
}

#define SA  20   // A smem row stride (words): LDSM rows hit distinct 4-bank groups
#define SBk 20   // B smem (n-major) row stride

// ---------------------------------------------------------------------------
// Stage 1: QKV GEMM (M=8192, K=1024, N=3072)
// block 128x128, BK=16, 8 warps (2x4), warp tile 64x32, ldmatrix feeds
// ---------------------------------------------------------------------------
__global__ __launch_bounds__(256, 2)
void gemm_qkv_kernel(const float* __restrict__ A,      // x [8192,1024]
                     const float* __restrict__ B,      // W_attn [1024,3072]
                     const float* __restrict__ b_attn,
                     const float* __restrict__ bQ,
                     const float* __restrict__ bK,
                     const float* __restrict__ bV)
{
    __shared__ unsigned As[128 * SA];   // [row 0..127][k 0..15]
    __shared__ unsigned Bs[128 * SBk];  // [n 0..127][k 0..15]  (n-major!)

    const int tid = threadIdx.x;
    const int wid = tid >> 5, lane = tid & 31;
    const int mBase = (wid >> 2) * 64, nBase = (wid & 3) * 32;
    const int cRow = blockIdx.y, cCol = blockIdx.x;
    const int g = lane >> 2, t = lane & 3;

    float acc[4][4][4] = {};

    const float* Ag = A + (size_t)cRow * 128 * 1024;
    const float* Bg = B + cCol * 128;

    // ldmatrix per-lane addresses (byte offsets into smem)
    const int rA = (lane & 7) + ((lane >> 3) & 1) * 8;   // bit3 -> row+8
    const int kA = ((lane >> 4) & 1) * 4;                // bit4 -> k+4
    const unsigned aAddr = sptr(As) + ((mBase + rA) * SA + kA) * 4;
    const int rB = (lane & 7) + ((lane >> 4) & 1) * 8;   // bit4 -> row+8
    const int kB = ((lane >> 3) & 1) * 4;                // bit3 -> k+4
    const unsigned bAddr = sptr(Bs) + ((nBase + rB) * SBk + kB) * 4;

    // fill-thread indices
    const int arow = tid >> 2, ac4 = tid & 3;      // A: rows arow, arow+64
    const int nB = tid & 127, kc0 = tid >> 7;      // B: n col, kc in {kc0, kc0+2}

    float4 pa0, pa1;
    float  pb[2][4];

    #define LDG_TILE(kb)                                                        \
        pa0 = *(const float4*)(Ag + (size_t)arow * 1024 + (kb) + ac4 * 4);      \
        pa1 = *(const float4*)(Ag + (size_t)(arow + 64) * 1024 + (kb) + ac4*4); \
        _Pragma("unroll")                                                       \
        for (int it = 0; it < 2; it++) {                                        \
            int kc = kc0 + it * 2;                                              \
            _Pragma("unroll")                                                   \
            for (int i = 0; i < 4; i++)                                         \
                pb[it][i] = Bg[(size_t)((kb) + kc * 4 + i) * 3072 + nB];        \
        }

    #define STS_TILE()                                                          \
        { unsigned* p = &As[arow * SA + ac4 * 4];                               \
          p[0]=f2t(pa0.x); p[1]=f2t(pa0.y); p[2]=f2t(pa0.z); p[3]=f2t(pa0.w);   \
          p = &As[(arow + 64) * SA + ac4 * 4];                                  \
          p[0]=f2t(pa1.x); p[1]=f2t(pa1.y); p[2]=f2t(pa1.z); p[3]=f2t(pa1.w);   \
          _Pragma("unroll")                                                     \
          for (int it = 0; it < 2; it++) {                                      \
              int kc = kc0 + it * 2;                                            \
              unsigned* q = &Bs[nB * SBk + kc * 4];                             \
              q[0]=f2t(pb[it][0]); q[1]=f2t(pb[it][1]);                         \
              q[2]=f2t(pb[it][2]); q[3]=f2t(pb[it][3]);                         \
          } }

    LDG_TILE(0)
    for (int kb = 0; kb < 1024; kb += 16) {
        STS_TILE()
        __syncthreads();
        if (kb + 16 < 1024) { LDG_TILE(kb + 16) }

        #pragma unroll
        for (int kk = 0; kk < 2; kk++) {
            const int k0 = kk * 8;
            unsigned af[4][4], bf[2][4];
            #pragma unroll
            for (int i = 0; i < 4; i++)
                ldsm4(af[i], aAddr + (i * 16 * SA + k0) * 4);
            #pragma unroll
            for (int jp = 0; jp < 2; jp++)
                ldsm4(bf[jp], bAddr + (jp * 16 * SBk + k0) * 4);
            #pragma unroll
            for (int i = 0; i < 4; i++)
                #pragma unroll
                for (int j = 0; j < 4; j++)
                    mma8(acc[i][j], af[i], &bf[j >> 1][(j & 1) * 2]);
        }
        __syncthreads();
    }
    #undef LDG_TILE
    #undef STS_TILE

    // epilogue: scatter q/k/v with fused biases + q scale
    const int colW  = cCol * 128 + nBase;
    const int which = colW >> 10;
    const int h     = (colW & 1023) >> 6;
    float* dstBase  = which == 0 ? g_q : (which == 1 ? g_k : g_v);
    const float* hb = (which == 0 ? bQ : (which == 1 ? bK : bV)) + h * 64;
    const float scale = (which == 0) ? 0.125f : 1.0f;

    #pragma unroll
    for (int j = 0; j < 4; j++) {
        int col = colW + j * 8 + t * 2;
        int d0 = col & 63;
        float bb0 = (b_attn[col]     + hb[d0])     * scale;
        float bb1 = (b_attn[col + 1] + hb[d0 + 1]) * scale;
        #pragma unroll
        for (int i = 0; i < 4; i++) {
            int row0 = cRow * 128 + mBase + i * 16 + g;
            #pragma unroll
            for (int rh = 0; rh < 2; rh++) {
                int row = row0 + rh * 8;
                int b = row >> 11, tt_ = row & 2047;
                float2 o;
                o.x = acc[i][j][rh * 2 + 0] * scale + bb0;
                o.y = acc[i][j][rh * 2 + 1] * scale + bb1;
                *(float2*)(dstBase + (((size_t)(b * HH + h) * TT + tt_) << 6) + d0) = o;
            }
        }
    }
}

// ---------------------------------------------------------------------------
// Stage 2: causal flash attention, tf32 mma, ldmatrix K/P fragment feeds
// block = 128 thr (4 warps); q-tile 64, warp owns 16 q-rows
// ---------------------------------------------------------------------------
#define SQ 68    // Ks/Ps row stride (68 mod 32 = 4 -> LDSM conflict-free)
#define SV 72    // Vs row stride (scalar V-frag loads conflict-free)

__global__ __launch_bounds__(128)
void attn_kernel()
{
    __shared__ unsigned Ks[64 * SQ];   // [kv][d]; aliased as per-warp P after S
    __shared__ unsigned Vs[64 * SV];   // [kv][d]

    const int tid = threadIdx.x;
    const int w = tid >> 5, lane = tid & 31;
    const int g = lane >> 2, t = lane & 3;
    const int bh = blockIdx.y, qt = blockIdx.x;
    const int q0 = qt * 64;

    const float* qbase = g_q + (size_t)bh * TT * 64;
    const float* kbase = g_k + (size_t)bh * TT * 64;
    const float* vbase = g_v + (size_t)bh * TT * 64;

    // Q fragments (pre-scaled) in regs
    unsigned qa[8][4];
    {
        const float* q0p = qbase + (size_t)(q0 + w * 16 + g) * 64;
        const float* q1p = q0p + 8 * 64;
        #pragma unroll
        for (int kk = 0; kk < 8; kk++) {
            qa[kk][0] = f2t(q0p[kk * 8 + t]);
            qa[kk][1] = f2t(q1p[kk * 8 + t]);
            qa[kk][2] = f2t(q0p[kk * 8 + t + 4]);
            qa[kk][3] = f2t(q1p[kk * 8 + t + 4]);
        }
    }

    float oacc[8][4] = {};
    float mrow[2] = {-1e30f, -1e30f};
    float lrow[2] = {0.f, 0.f};

    unsigned* Psw = Ks + w * 16 * SQ;

    // ldmatrix lane addresses
    const int rBf = (lane & 7) + ((lane >> 4) & 1) * 8;   // B-op: bit4 -> row+8
    const int kBf = ((lane >> 3) & 1) * 4;                // bit3 -> k+4
    const unsigned kAddr = sptr(Ks) + (rBf * SQ + kBf) * 4;
    const int rAf = (lane & 7) + ((lane >> 3) & 1) * 8;   // A-op: bit3 -> row+8
    const int kAf = ((lane >> 4) & 1) * 4;                // bit4 -> k+4
    const unsigned pAddr = sptr(Psw) + (rAf * SQ + kAf) * 4;

    for (int tI = 0; tI <= qt; tI++) {
        __syncthreads();
        const float* kt = kbase + (size_t)tI * 64 * 64;
        const float* vt = vbase + (size_t)tI * 64 * 64;
        #pragma unroll
        for (int i = 0; i < 8; i++) {
            int id = tid + i * 128;
            int r = id >> 4, c4 = id & 15;
            float4 kv = *(const float4*)(kt + r * 64 + c4 * 4);
            float4 vv = *(const float4*)(vt + r * 64 + c4 * 4);
            unsigned* kp = &Ks[r * SQ + c4 * 4];
            kp[0]=f2t(kv.x); kp[1]=f2t(kv.y); kp[2]=f2t(kv.z); kp[3]=f2t(kv.w);
            unsigned* vp = &Vs[r * SV + c4 * 4];
            vp[0]=f2t(vv.x); vp[1]=f2t(vv.y); vp[2]=f2t(vv.z); vp[3]=f2t(vv.w);
        }
        __syncthreads();

        // S = Q . K^T  (16 x 64 per warp)
        float sacc[8][4] = {};
        #pragma unroll
        for (int kk = 0; kk < 8; kk++) {
            const int k0 = kk * 8;
            #pragma unroll
            for (int jp = 0; jp < 4; jp++) {
                unsigned kf[4];
                ldsm4(kf, kAddr + (jp * 16 * SQ + k0) * 4);
                mma8(sacc[jp * 2 + 0], qa[kk], &kf[0]);
                mma8(sacc[jp * 2 + 1], qa[kk], &kf[2]);
            }
        }
        __syncthreads();   // Ks reads done -> safe to overwrite as P

        if (tI == qt) {
            #pragma unroll
            for (int j = 0; j < 8; j++)
                #pragma unroll
                for (int r = 0; r < 4; r++) {
                    int rq = w * 16 + g + (r >> 1) * 8;
                    int cq = j * 8 + t * 2 + (r & 1);
                    if (cq > rq) sacc[j][r] = -1e30f;
                }
        }

        // online softmax
        float corr[2];
        #pragma unroll
        for (int rh = 0; rh < 2; rh++) {
            float mt = -1e30f;
            #pragma unroll
            for (int j = 0; j < 8; j++)
                mt = fmaxf(mt, fmaxf(sacc[j][rh * 2], sacc[j][rh * 2 + 1]));
            mt = fmaxf(mt, __shfl_xor_sync(0xffffffffu, mt, 1));
            mt = fmaxf(mt, __shfl_xor_sync(0xffffffffu, mt, 2));
            float mn = fmaxf(mrow[rh], mt);
            corr[rh] = __expf(mrow[rh] - mn);
            mrow[rh] = mn;
        }
        float ls0 = 0.f, ls1 = 0.f;
        #pragma unroll
        for (int j = 0; j < 8; j++) {
            float p0 = __expf(sacc[j][0] - mrow[0]);
            float p1 = __expf(sacc[j][1] - mrow[0]);
            float p2 = __expf(sacc[j][2] - mrow[1]);
            float p3 = __expf(sacc[j][3] - mrow[1]);
            sacc[j][0] = p0; sacc[j][1] = p1; sacc[j][2] = p2; sacc[j][3] = p3;
            ls0 += p0 + p1; ls1 += p2 + p3;
        }
        ls0 += __shfl_xor_sync(0xffffffffu, ls0, 1);
        ls0 += __shfl_xor_sync(0xffffffffu, ls0, 2);
        ls1 += __shfl_xor_sync(0xffffffffu, ls1, 1);
        ls1 += __shfl_xor_sync(0xffffffffu, ls1, 2);
        lrow[0] = lrow[0] * corr[0] + ls0;
        lrow[1] = lrow[1] * corr[1] + ls1;

        #pragma unroll
        for (int j = 0; j < 8; j++) {
            oacc[j][0] *= corr[0]; oacc[j][1] *= corr[0];
            oacc[j][2] *= corr[1]; oacc[j][3] *= corr[1];
        }

        // P -> per-warp smem (tf32)
        #pragma unroll
        for (int j = 0; j < 8; j++) {
            unsigned* p0 = &Psw[g * SQ + j * 8 + t * 2];
            p0[0] = f2t(sacc[j][0]); p0[1] = f2t(sacc[j][1]);
            unsigned* p1 = &Psw[(g + 8) * SQ + j * 8 + t * 2];
            p1[0] = f2t(sacc[j][2]); p1[1] = f2t(sacc[j][3]);
        }
        __syncwarp();

        // O += P . V   (P via ldmatrix, V scalar conflict-free)
        #pragma unroll
        for (int kk = 0; kk < 8; kk++) {
            const int k0 = kk * 8;
            unsigned pa[4];
            ldsm4(pa, pAddr + k0 * 4);
            #pragma unroll
            for (int j = 0; j < 8; j++) {
                unsigned vb[2];
                vb[0] = Vs[(k0 + t) * SV + j * 8 + g];
                vb[1] = Vs[(k0 + t + 4) * SV + j * 8 + g];
                mma8(oacc[j], pa, vb);
            }
        }
    }

    // write y [B,T,C]
    const int b = bh >> 4, h = bh & 15;
    const float inv0 = 1.f / lrow[0], inv1 = 1.f / lrow[1];
    float* yb = g_y + ((size_t)b * TT + q0 + w * 16) * 1024 + h * 64;
    #pragma unroll
    for (int j = 0; j < 8; j++) {
        float2 o0 = { oacc[j][0] * inv0, oacc[j][1] * inv0 };
        float2 o1 = { oacc[j][2] * inv1, oacc[j][3] * inv1 };
        *(float2*)(yb + (size_t)g * 1024 + j * 8 + t * 2) = o0;
        *(float2*)(yb + (size_t)(g + 8) * 1024 + j * 8 + t * 2) = o1;
    }
}

// ---------------------------------------------------------------------------
// Stage 3: out = y @ W_proj + b_proj  (M=8192, K=1024, N=1024)
// ---------------------------------------------------------------------------
__global__ __launch_bounds__(256, 2)
void gemm_proj_kernel(const float* __restrict__ B,      // W_proj [1024,1024]
                      const float* __restrict__ b_proj,
                      float* __restrict__ out)
{
    __shared__ unsigned As[128 * SA];
    __shared__ unsigned Bs[128 * SBk];

    const int tid = threadIdx.x;
    const int wid = tid >> 5, lane = tid & 31;
    const int mBase = (wid >> 2) * 64, nBase = (wid & 3) * 32;
    const int cRow = blockIdx.y, cCol = blockIdx.x;
    const int g = lane >> 2, t = lane & 3;

    float acc[4][4][4] = {};

    const float* Ag = g_y + (size_t)cRow * 128 * 1024;
    const float* Bg = B + cCol * 128;

    const int rA = (lane & 7) + ((lane >> 3) & 1) * 8;
    const int kA = ((lane >> 4) & 1) * 4;
    const unsigned aAddr = sptr(As) + ((mBase + rA) * SA + kA) * 4;
    const int rB = (lane & 7) + ((lane >> 4) & 1) * 8;
    const int kB = ((lane >> 3) & 1) * 4;
    const unsigned bAddr = sptr(Bs) + ((nBase + rB) * SBk + kB) * 4;

    const int arow = tid >> 2, ac4 = tid & 3;
    const int nB = tid & 127, kc0 = tid >> 7;

    float4 pa0, pa1;
    float  pb[2][4];

    #define LDG_TILE(kb)                                                        \
        pa0 = *(const float4*)(Ag + (size_t)arow * 1024 + (kb) + ac4 * 4);      \
        pa1 = *(const float4*)(Ag + (size_t)(arow + 64) * 1024 + (kb) + ac4*4); \
        _Pragma("unroll")                                                       \
        for (int it = 0; it < 2; it++) {                                        \
            int kc = kc0 + it * 2;                                              \
            _Pragma("unroll")                                                   \
            for (int i = 0; i < 4; i++)                                         \
                pb[it][i] = Bg[(size_t)((kb) + kc * 4 + i) * 1024 + nB];        \
        }

    #define STS_TILE()                                                          \
        { unsigned* p = &As[arow * SA + ac4 * 4];                               \
          p[0]=f2t(pa0.x); p[1]=f2t(pa0.y); p[2]=f2t(pa0.z); p[3]=f2t(pa0.w);   \
          p = &As[(arow + 64) * SA + ac4 * 4];                                  \
          p[0]=f2t(pa1.x); p[1]=f2t(pa1.y); p[2]=f2t(pa1.z); p[3]=f2t(pa1.w);   \
          _Pragma("unroll")                                                     \
          for (int it = 0; it < 2; it++) {                                      \
              int kc = kc0 + it * 2;                                            \
              unsigned* q = &Bs[nB * SBk + kc * 4];                             \
              q[0]=f2t(pb[it][0]); q[1]=f2t(pb[it][1]);                         \
              q[2]=f2t(pb[it][2]); q[3]=f2t(pb[it][3]);                         \
          } }

    LDG_TILE(0)
    for (int kb = 0; kb < 1024; kb += 16) {
        STS_TILE()
        __syncthreads();
        if (kb + 16 < 1024) { LDG_TILE(kb + 16) }

        #pragma unroll
        for (int kk = 0; kk < 2; kk++) {
            const int k0 = kk * 8;
            unsigned af[4][4], bf[2][4];
            #pragma unroll
            for (int i = 0; i < 4; i++)
                ldsm4(af[i], aAddr + (i * 16 * SA + k0) * 4);
            #pragma unroll
            for (int jp = 0; jp < 2; jp++)
                ldsm4(bf[jp], bAddr + (jp * 16 * SBk + k0) * 4);
            #pragma unroll
            for (int i = 0; i < 4; i++)
                #pragma unroll
                for (int j = 0; j < 4; j++)
                    mma8(acc[i][j], af[i], &bf[j >> 1][(j & 1) * 2]);
        }
        __syncthreads();
    }
    #undef LDG_TILE
    #undef STS_TILE

    #pragma unroll
    for (int j = 0; j < 4; j++) {
        int col = cCol * 128 + nBase + j * 8 + t * 2;
        float bb0 = b_proj[col], bb1 = b_proj[col + 1];
        #pragma unroll
        for (int i = 0; i < 4; i++) {
            int row0 = cRow * 128 + mBase + i * 16 + g;
            #pragma unroll
            for (int rh = 0; rh < 2; rh++) {
                int row = row0 + rh * 8;
                float2 o;
                o.x = acc[i][j][rh * 2 + 0] + bb0;
                o.y = acc[i][j][rh * 2 + 1] + bb1;
                *(float2*)(out + (size_t)row * 1024 + col) = o;
            }
        }
    }
}

// ---------------------------------------------------------------------------
extern "C" void kernel_launch(void* const* d_in, const int* in_sizes, int n_in,
                              void* d_out, int out_size)
{
    (void)in_sizes; (void)n_in; (void)out_size;
    const float* x      = (const float*)d_in[0];
    const float* W_attn = (const float*)d_in[1];
    const float* b_attn = (const float*)d_in[2];
    const float* W_proj = (const float*)d_in[3];
    const float* b_proj = (const float*)d_in[4];
    const float* bQ     = (const float*)d_in[5];
    const float* bK     = (const float*)d_in[6];
    const float* bV     = (const float*)d_in[7];
    float* out = (float*)d_out;

    dim3 g1(24, 64);
    gemm_qkv_kernel<<<g1, 256>>>(x, W_attn, b_attn, bQ, bK, bV);

    dim3 ga(TT / 64, 4 * HH);
    attn_kernel<<<ga, 128>>>();

    dim3 g2(8, 64);
    gemm_proj_kernel<<<g2, 256>>>(W_proj, b_proj, out);
}

// round 7
// speedup vs baseline: 9.9504x; 1.0308x over previous
#include <cuda_runtime.h>

// ---------------------------------------------------------------------------
// CausalSelfAttentionWithBias: B=4, T=2048, C=1024, H=16, D=64
// tf32 mma.m16n8k8; operands pre-rounded to tf32 once; cp.async 2-stage GEMMs.
// ---------------------------------------------------------------------------

#define TT 2048
#define HH 16

__device__ float g_q[4 * HH * TT * 64];
__device__ float g_k[4 * HH * TT * 64];
__device__ float g_v[4 * HH * TT * 64];
__device__ float g_y[4 * TT * 1024];
__device__ float g_x[4 * TT * 1024];      // x rounded to tf32
__device__ float g_wa[1024 * 3072];       // W_attn rounded
__device__ float g_wp[1024 * 1024];       // W_proj rounded

__device__ __forceinline__ unsigned f2t(float x) {
    unsigned u; asm("cvt.rna.tf32.f32 %0, %1;" : "=r"(u) : "f"(x)); return u;
}

__device__ __forceinline__ void mma8(float* d, const unsigned* a, const unsigned* b) {
    asm volatile(
        "mma.sync.aligned.m16n8k8.row.col.f32.tf32.tf32.f32 "
        "{%0,%1,%2,%3}, {%4,%5,%6,%7}, {%8,%9}, {%0,%1,%2,%3};"
        : "+f"(d[0]), "+f"(d[1]), "+f"(d[2]), "+f"(d[3])
        : "r"(a[0]), "r"(a[1]), "r"(a[2]), "r"(a[3]), "r"(b[0]), "r"(b[1]));
}

__device__ __forceinline__ unsigned sptr(const void* p) {
    return (unsigned)__cvta_generic_to_shared(p);
}

__device__ __forceinline__ void ldsm4(unsigned* r, unsigned addr) {
    asm volatile("ldmatrix.sync.aligned.m8n8.x4.shared.b16 {%0,%1,%2,%3}, [%4];"
        : "=r"(r[0]), "=r"(r[1]), "=r"(r[2]), "=r"(r[3]) : "r"(addr));
}

__device__ __forceinline__ void cpa16(unsigned dst, const void* src) {
    asm volatile("cp.async.cg.shared.global [%0], [%1], 16;" :: "r"(dst), "l"(src));
}
__device__ __forceinline__ void cp_commit() {
    asm volatile("cp.async.commit_group;");
}
template <int N> __device__ __forceinline__ void cp_wait() {
    asm volatile("cp.async.wait_group %0;" :: "n"(N));
}

// ---------------------------------------------------------------------------
// Prepass: round fp32 -> tf32-valued fp32 (vectorized)
// ---------------------------------------------------------------------------
__global__ void cvt_kernel(const float* __restrict__ src, float* __restrict__ dst, int n4)
{
    int i = blockIdx.x * blockDim.x + threadIdx.x;
    if (i < n4) {
        float4 v = ((const float4*)src)[i];
        v.x = __uint_as_float(f2t(v.x));
        v.y = __uint_as_float(f2t(v.y));
        v.z = __uint_as_float(f2t(v.z));
        v.w = __uint_as_float(f2t(v.w));
        ((float4*)dst)[i] = v;
    }
}

#define SA 20    // A smem row stride (words)
#define SB 136   // B smem (k-major) row stride (words)
#define A_STG (128 * SA)   // words per A stage
#define B_STG (16 * SB)    // words per B stage

// ---------------------------------------------------------------------------
// GEMM core (shared by qkv and proj): 128x128 block, BK=16, 2-stage cp.async,
// 8 warps (2x4), warp tile 64x32. A via ldmatrix, B via conflict-free LDS.
// ---------------------------------------------------------------------------
#define GEMM_BODY(LDB_, Ag_, Bg_)                                               \
    __shared__ unsigned As[2 * A_STG];                                          \
    __shared__ unsigned Bs[2 * B_STG];                                          \
    const int tid = threadIdx.x;                                                \
    const int wid = tid >> 5, lane = tid & 31;                                  \
    const int mBase = (wid >> 2) * 64, nBase = (wid & 3) * 32;                  \
    const int g = lane >> 2, t = lane & 3;                                      \
    float acc[4][4][4] = {};                                                    \
    const unsigned sAs = sptr(As), sBs = sptr(Bs);                              \
    const int rA = (lane & 7) + ((lane >> 3) & 1) * 8;                          \
    const int kA = ((lane >> 4) & 1) * 4;                                       \
    const unsigned aOff = (mBase + rA) * SA + kA;                               \
    const int ar = tid >> 2, ac4 = tid & 3;                                     \
    const int bk = tid >> 5, bc = tid & 31;                                     \
    /* prologue fill stage 0 */                                                 \
    {                                                                           \
        cpa16(sAs + (ar * SA + ac4 * 4) * 4, Ag_ + (size_t)ar * 1024 + ac4 * 4);        \
        cpa16(sAs + ((ar + 64) * SA + ac4 * 4) * 4, Ag_ + (size_t)(ar + 64) * 1024 + ac4 * 4); \
        cpa16(sBs + (bk * SB + bc * 4) * 4, Bg_ + (size_t)bk * LDB_ + bc * 4);          \
        cpa16(sBs + ((bk + 8) * SB + bc * 4) * 4, Bg_ + (size_t)(bk + 8) * LDB_ + bc * 4); \
        cp_commit();                                                            \
    }                                                                           \
    for (int i = 0; i < 64; i++) {                                              \
        const int s = i & 1;                                                    \
        if (i + 1 < 64) {                                                       \
            const int kb = (i + 1) * 16;                                        \
            const int so = (s ^ 1);                                             \
            cpa16(sAs + (so * A_STG + ar * SA + ac4 * 4) * 4,                   \
                  Ag_ + (size_t)ar * 1024 + kb + ac4 * 4);                      \
            cpa16(sAs + (so * A_STG + (ar + 64) * SA + ac4 * 4) * 4,            \
                  Ag_ + (size_t)(ar + 64) * 1024 + kb + ac4 * 4);               \
            cpa16(sBs + (so * B_STG + bk * SB + bc * 4) * 4,                    \
                  Bg_ + (size_t)(kb + bk) * LDB_ + bc * 4);                     \
            cpa16(sBs + (so * B_STG + (bk + 8) * SB + bc * 4) * 4,              \
                  Bg_ + (size_t)(kb + bk + 8) * LDB_ + bc * 4);                 \
            cp_commit();                                                        \
            cp_wait<1>();                                                       \
        } else {                                                                \
            cp_wait<0>();                                                       \
        }                                                                       \
        __syncthreads();                                                        \
        const unsigned aS = sAs + s * A_STG * 4;                                \
        const unsigned* BsS = Bs + s * B_STG;                                   \
        _Pragma("unroll")                                                       \
        for (int kk = 0; kk < 2; kk++) {                                        \
            const int k0 = kk * 8;                                              \
            unsigned af[4][4], bf[4][2];                                        \
            _Pragma("unroll")                                                   \
            for (int ii = 0; ii < 4; ii++)                                      \
                ldsm4(af[ii], aS + (aOff + ii * 16 * SA + k0) * 4);             \
            _Pragma("unroll")                                                   \
            for (int j = 0; j < 4; j++) {                                       \
                const int c0 = nBase + j * 8 + g;                               \
                bf[j][0] = BsS[(k0 + t) * SB + c0];                             \
                bf[j][1] = BsS[(k0 + t + 4) * SB + c0];                         \
            }                                                                   \
            _Pragma("unroll")                                                   \
            for (int ii = 0; ii < 4; ii++)                                      \
                _Pragma("unroll")                                               \
                for (int j = 0; j < 4; j++)                                     \
                    mma8(acc[ii][j], af[ii], bf[j]);                            \
        }                                                                       \
        __syncthreads();                                                        \
    }

// ---------------------------------------------------------------------------
// Stage 1: QKV GEMM (M=8192, K=1024, N=3072), scatter epilogue (tf32-rounded)
// ---------------------------------------------------------------------------
__global__ __launch_bounds__(256, 2)
void gemm_qkv_kernel(const float* __restrict__ b_attn,
                     const float* __restrict__ bQ,
                     const float* __restrict__ bK,
                     const float* __restrict__ bV)
{
    const int cRow = blockIdx.y, cCol = blockIdx.x;
    const float* Ag = g_x + (size_t)cRow * 128 * 1024;
    const float* Bg = g_wa + cCol * 128;

    GEMM_BODY(3072, Ag, Bg)

    const int colW  = cCol * 128 + nBase;
    const int which = colW >> 10;
    const int h     = (colW & 1023) >> 6;
    float* dstBase  = which == 0 ? g_q : (which == 1 ? g_k : g_v);
    const float* hb = (which == 0 ? bQ : (which == 1 ? bK : bV)) + h * 64;
    const float scale = (which == 0) ? 0.125f : 1.0f;

    #pragma unroll
    for (int j = 0; j < 4; j++) {
        int col = colW + j * 8 + t * 2;
        int d0 = col & 63;
        float bb0 = (b_attn[col]     + hb[d0])     * scale;
        float bb1 = (b_attn[col + 1] + hb[d0 + 1]) * scale;
        #pragma unroll
        for (int ii = 0; ii < 4; ii++) {
            int row0 = cRow * 128 + mBase + ii * 16 + g;
            #pragma unroll
            for (int rh = 0; rh < 2; rh++) {
                int row = row0 + rh * 8;
                int b = row >> 11, tt_ = row & 2047;
                float2 o;
                o.x = __uint_as_float(f2t(acc[ii][j][rh * 2 + 0] * scale + bb0));
                o.y = __uint_as_float(f2t(acc[ii][j][rh * 2 + 1] * scale + bb1));
                *(float2*)(dstBase + (((size_t)(b * HH + h) * TT + tt_) << 6) + d0) = o;
            }
        }
    }
}

// ---------------------------------------------------------------------------
// Stage 2: causal flash attention; K/V fill via cp.async (data pre-rounded)
// ---------------------------------------------------------------------------
#define SQ 68
#define SV 72

__global__ __launch_bounds__(128)
void attn_kernel()
{
    __shared__ unsigned Ks[64 * SQ];   // [kv][d]; aliased as per-warp P after S
    __shared__ unsigned Vs[64 * SV];

    const int tid = threadIdx.x;
    const int w = tid >> 5, lane = tid & 31;
    const int g = lane >> 2, t = lane & 3;
    const int bh = blockIdx.y, qt = blockIdx.x;
    const int q0 = qt * 64;

    const float* qbase = g_q + (size_t)bh * TT * 64;
    const float* kbase = g_k + (size_t)bh * TT * 64;
    const float* vbase = g_v + (size_t)bh * TT * 64;

    // Q fragments: already tf32-valued -> bit loads
    unsigned qa[8][4];
    {
        const float* q0p = qbase + (size_t)(q0 + w * 16 + g) * 64;
        const float* q1p = q0p + 8 * 64;
        #pragma unroll
        for (int kk = 0; kk < 8; kk++) {
            qa[kk][0] = __float_as_uint(q0p[kk * 8 + t]);
            qa[kk][1] = __float_as_uint(q1p[kk * 8 + t]);
            qa[kk][2] = __float_as_uint(q0p[kk * 8 + t + 4]);
            qa[kk][3] = __float_as_uint(q1p[kk * 8 + t + 4]);
        }
    }

    float oacc[8][4] = {};
    float mrow[2] = {-1e30f, -1e30f};
    float lrow[2] = {0.f, 0.f};

    unsigned* Psw = Ks + w * 16 * SQ;
    const unsigned sKs = sptr(Ks), sVs = sptr(Vs);

    const int rBf = (lane & 7) + ((lane >> 4) & 1) * 8;
    const int kBf = ((lane >> 3) & 1) * 4;
    const unsigned kAddr = sKs + (rBf * SQ + kBf) * 4;
    const int rAf = (lane & 7) + ((lane >> 3) & 1) * 8;
    const int kAf = ((lane >> 4) & 1) * 4;
    const unsigned pAddr = sptr(Psw) + (rAf * SQ + kAf) * 4;

    for (int tI = 0; tI <= qt; tI++) {
        __syncthreads();   // prior tile's P/V reads complete
        const float* kt = kbase + (size_t)tI * 64 * 64;
        const float* vt = vbase + (size_t)tI * 64 * 64;
        #pragma unroll
        for (int i = 0; i < 8; i++) {
            int id = tid + i * 128;
            int r = id >> 4, c4 = id & 15;
            cpa16(sKs + (r * SQ + c4 * 4) * 4, kt + r * 64 + c4 * 4);
            cpa16(sVs + (r * SV + c4 * 4) * 4, vt + r * 64 + c4 * 4);
        }
        cp_commit();
        cp_wait<0>();
        __syncthreads();

        // S = Q . K^T
        float sacc[8][4] = {};
        #pragma unroll
        for (int kk = 0; kk < 8; kk++) {
            const int k0 = kk * 8;
            #pragma unroll
            for (int jp = 0; jp < 4; jp++) {
                unsigned kf[4];
                ldsm4(kf, kAddr + (jp * 16 * SQ + k0) * 4);
                mma8(sacc[jp * 2 + 0], qa[kk], &kf[0]);
                mma8(sacc[jp * 2 + 1], qa[kk], &kf[2]);
            }
        }
        __syncthreads();   // Ks reads done -> safe to overwrite as P

        if (tI == qt) {
            #pragma unroll
            for (int j = 0; j < 8; j++)
                #pragma unroll
                for (int r = 0; r < 4; r++) {
                    int rq = w * 16 + g + (r >> 1) * 8;
                    int cq = j * 8 + t * 2 + (r & 1);
                    if (cq > rq) sacc[j][r] = -1e30f;
                }
        }

        // online softmax
        float corr[2];
        #pragma unroll
        for (int rh = 0; rh < 2; rh++) {
            float mt = -1e30f;
            #pragma unroll
            for (int j = 0; j < 8; j++)
                mt = fmaxf(mt, fmaxf(sacc[j][rh * 2], sacc[j][rh * 2 + 1]));
            mt = fmaxf(mt, __shfl_xor_sync(0xffffffffu, mt, 1));
            mt = fmaxf(mt, __shfl_xor_sync(0xffffffffu, mt, 2));
            float mn = fmaxf(mrow[rh], mt);
            corr[rh] = __expf(mrow[rh] - mn);
            mrow[rh] = mn;
        }
        float ls0 = 0.f, ls1 = 0.f;
        #pragma unroll
        for (int j = 0; j < 8; j++) {
            float p0 = __expf(sacc[j][0] - mrow[0]);
            float p1 = __expf(sacc[j][1] - mrow[0]);
            float p2 = __expf(sacc[j][2] - mrow[1]);
            float p3 = __expf(sacc[j][3] - mrow[1]);
            sacc[j][0] = p0; sacc[j][1] = p1; sacc[j][2] = p2; sacc[j][3] = p3;
            ls0 += p0 + p1; ls1 += p2 + p3;
        }
        ls0 += __shfl_xor_sync(0xffffffffu, ls0, 1);
        ls0 += __shfl_xor_sync(0xffffffffu, ls0, 2);
        ls1 += __shfl_xor_sync(0xffffffffu, ls1, 1);
        ls1 += __shfl_xor_sync(0xffffffffu, ls1, 2);
        lrow[0] = lrow[0] * corr[0] + ls0;
        lrow[1] = lrow[1] * corr[1] + ls1;

        #pragma unroll
        for (int j = 0; j < 8; j++) {
            oacc[j][0] *= corr[0]; oacc[j][1] *= corr[0];
            oacc[j][2] *= corr[1]; oacc[j][3] *= corr[1];
        }

        // P -> per-warp smem (tf32)
        #pragma unroll
        for (int j = 0; j < 8; j++) {
            unsigned* p0 = &Psw[g * SQ + j * 8 + t * 2];
            p0[0] = f2t(sacc[j][0]); p0[1] = f2t(sacc[j][1]);
            unsigned* p1 = &Psw[(g + 8) * SQ + j * 8 + t * 2];
            p1[0] = f2t(sacc[j][2]); p1[1] = f2t(sacc[j][3]);
        }
        __syncwarp();

        // O += P . V
        #pragma unroll
        for (int kk = 0; kk < 8; kk++) {
            const int k0 = kk * 8;
            unsigned pa[4];
            ldsm4(pa, pAddr + k0 * 4);
            #pragma unroll
            for (int j = 0; j < 8; j++) {
                unsigned vb[2];
                vb[0] = Vs[(k0 + t) * SV + j * 8 + g];
                vb[1] = Vs[(k0 + t + 4) * SV + j * 8 + g];
                mma8(oacc[j], pa, vb);
            }
        }
    }

    // write y [B,T,C] rounded to tf32 (proj consumes it directly)
    const int b = bh >> 4, h = bh & 15;
    const float inv0 = 1.f / lrow[0], inv1 = 1.f / lrow[1];
    float* yb = g_y + ((size_t)b * TT + q0 + w * 16) * 1024 + h * 64;
    #pragma unroll
    for (int j = 0; j < 8; j++) {
        float2 o0, o1;
        o0.x = __uint_as_float(f2t(oacc[j][0] * inv0));
        o0.y = __uint_as_float(f2t(oacc[j][1] * inv0));
        o1.x = __uint_as_float(f2t(oacc[j][2] * inv1));
        o1.y = __uint_as_float(f2t(oacc[j][3] * inv1));
        *(float2*)(yb + (size_t)g * 1024 + j * 8 + t * 2) = o0;
        *(float2*)(yb + (size_t)(g + 8) * 1024 + j * 8 + t * 2) = o1;
    }
}

// ---------------------------------------------------------------------------
// Stage 3: out = y @ W_proj + b_proj  (M=8192, K=1024, N=1024)
// ---------------------------------------------------------------------------
__global__ __launch_bounds__(256, 2)
void gemm_proj_kernel(const float* __restrict__ b_proj,
                      float* __restrict__ out)
{
    const int cRow = blockIdx.y, cCol = blockIdx.x;
    const float* Ag = g_y + (size_t)cRow * 128 * 1024;
    const float* Bg = g_wp + cCol * 128;

    GEMM_BODY(1024, Ag, Bg)

    #pragma unroll
    for (int j = 0; j < 4; j++) {
        int col = cCol * 128 + nBase + j * 8 + t * 2;
        float bb0 = b_proj[col], bb1 = b_proj[col + 1];
        #pragma unroll
        for (int ii = 0; ii < 4; ii++) {
            int row0 = cRow * 128 + mBase + ii * 16 + g;
            #pragma unroll
            for (int rh = 0; rh < 2; rh++) {
                int row = row0 + rh * 8;
                float2 o;
                o.x = acc[ii][j][rh * 2 + 0] + bb0;
                o.y = acc[ii][j][rh * 2 + 1] + bb1;
                *(float2*)(out + (size_t)row * 1024 + col) = o;
            }
        }
    }
}

// ---------------------------------------------------------------------------
extern "C" void kernel_launch(void* const* d_in, const int* in_sizes, int n_in,
                              void* d_out, int out_size)
{
    (void)in_sizes; (void)n_in; (void)out_size;
    const float* x      = (const float*)d_in[0];
    const float* W_attn = (const float*)d_in[1];
    const float* b_attn = (const float*)d_in[2];
    const float* W_proj = (const float*)d_in[3];
    const float* b_proj = (const float*)d_in[4];
    const float* bQ     = (const float*)d_in[5];
    const float* bK     = (const float*)d_in[6];
    const float* bV     = (const float*)d_in[7];
    float* out = (float*)d_out;

    float *p_x, *p_wa, *p_wp;
    cudaGetSymbolAddress((void**)&p_x,  g_x);
    cudaGetSymbolAddress((void**)&p_wa, g_wa);
    cudaGetSymbolAddress((void**)&p_wp, g_wp);

    // prepass: round inputs to tf32 (once)
    cvt_kernel<<<(2097152 + 255) / 256, 256>>>(x,      p_x,  2097152);  // 8192*1024/4
    cvt_kernel<<<(786432  + 255) / 256, 256>>>(W_attn, p_wa, 786432);   // 1024*3072/4
    cvt_kernel<<<(262144  + 255) / 256, 256>>>(W_proj, p_wp, 262144);   // 1024*1024/4

    dim3 g1(24, 64);
    gemm_qkv_kernel<<<g1, 256>>>(b_attn, bQ, bK, bV);

    dim3 ga(TT / 64, 4 * HH);
    attn_kernel<<<ga, 128>>>();

    dim3 g2(8, 64);
    gemm_proj_kernel<<<g2, 256>>>(b_proj, out);
}